// round 4
// baseline (speedup 1.0000x reference)
#include <cuda_runtime.h>
#include <cuda_bf16.h>
#include <cstdint>

// Problem constants
constexpr int T_ = 512;
constexpr int B_ = 64;
constexpr int H_ = 512;
constexpr int K_ = 16;
constexpr int M_ = T_ * B_;   // 32768 rows

// Scratch (device globals — no allocation allowed)
__device__ float g_h[(size_t)M_ * H_];    // 64 MB: relu(hidden@W1+b1)
__device__ float g_em[(size_t)M_ * K_];   // 2 MB : h@W2+b2
__device__ float g_diff[B_];              // per-batch fwd - gold

// ---------------------------------------------------------------------------
// GEMM1: h = relu(hidden @ W1 + b1)
// M=32768, K=512, N=512.  BM=128, BN=128, BK=16, 256 threads, 8x8 microtile.
// ---------------------------------------------------------------------------
#define BM 128
#define BN 128
#define BK 16

__global__ __launch_bounds__(256) void gemm1_kernel(
    const float* __restrict__ A,      // hidden  (M x H)
    const float* __restrict__ W,      // W1      (H x H)
    const float* __restrict__ bias)   // b1      (H)
{
    __shared__ float As[BK][BM + 4];  // +4 pad to soften store conflicts
    __shared__ float Bs[BK][BN];

    const int bm = blockIdx.y * BM;
    const int bn = blockIdx.x * BN;
    const int tid = threadIdx.x;
    const int tx = tid & 15;          // column group 0..15
    const int ty = tid >> 4;          // row group    0..15

    float acc[8][8];
#pragma unroll
    for (int i = 0; i < 8; i++)
#pragma unroll
        for (int j = 0; j < 8; j++) acc[i][j] = 0.f;

    for (int k0 = 0; k0 < H_; k0 += BK) {
        // Load A tile (BM x BK) -> As transposed. 512 float4, 2 per thread.
#pragma unroll
        for (int l = 0; l < 2; l++) {
            int idx  = tid + l * 256;        // 0..511
            int row  = idx >> 2;             // 0..127
            int col4 = idx & 3;              // 0..3
            float4 v = *(const float4*)&A[(size_t)(bm + row) * H_ + k0 + col4 * 4];
            As[col4 * 4 + 0][row] = v.x;
            As[col4 * 4 + 1][row] = v.y;
            As[col4 * 4 + 2][row] = v.z;
            As[col4 * 4 + 3][row] = v.w;
        }
        // Load B tile (BK x BN). 512 float4, 2 per thread.
#pragma unroll
        for (int l = 0; l < 2; l++) {
            int idx = tid + l * 256;
            int row = idx >> 5;              // 0..15
            int c4  = idx & 31;              // 0..31
            float4 v = *(const float4*)&W[(size_t)(k0 + row) * H_ + bn + c4 * 4];
            *(float4*)&Bs[row][c4 * 4] = v;
        }
        __syncthreads();

#pragma unroll
        for (int kk = 0; kk < BK; kk++) {
            float a[8], b[8];
#pragma unroll
            for (int i = 0; i < 8; i++) a[i] = As[kk][ty * 8 + i];
#pragma unroll
            for (int j = 0; j < 8; j++) b[j] = Bs[kk][tx * 8 + j];
#pragma unroll
            for (int i = 0; i < 8; i++)
#pragma unroll
                for (int j = 0; j < 8; j++)
                    acc[i][j] = fmaf(a[i], b[j], acc[i][j]);
        }
        __syncthreads();
    }

    // Epilogue: bias + relu, vectorized stores
    float bv[8];
#pragma unroll
    for (int j = 0; j < 8; j++) bv[j] = bias[bn + tx * 8 + j];

#pragma unroll
    for (int i = 0; i < 8; i++) {
        int row = bm + ty * 8 + i;
        float4 v0, v1;
        v0.x = fmaxf(acc[i][0] + bv[0], 0.f);
        v0.y = fmaxf(acc[i][1] + bv[1], 0.f);
        v0.z = fmaxf(acc[i][2] + bv[2], 0.f);
        v0.w = fmaxf(acc[i][3] + bv[3], 0.f);
        v1.x = fmaxf(acc[i][4] + bv[4], 0.f);
        v1.y = fmaxf(acc[i][5] + bv[5], 0.f);
        v1.z = fmaxf(acc[i][6] + bv[6], 0.f);
        v1.w = fmaxf(acc[i][7] + bv[7], 0.f);
        float* dst = &g_h[(size_t)row * H_ + bn + tx * 8];
        *(float4*)(dst + 0) = v0;
        *(float4*)(dst + 4) = v1;
    }
}

// ---------------------------------------------------------------------------
// GEMM2: em = h @ W2 + b2   (M x 512) @ (512 x 16)
// One thread per output row; W2 rows read uniformly (warp-broadcast via L1).
// ---------------------------------------------------------------------------
__global__ __launch_bounds__(256) void gemm2_kernel(
    const float* __restrict__ W2,     // (H x K)
    const float* __restrict__ b2)     // (K)
{
    const int m = blockIdx.x * 256 + threadIdx.x;
    const float* hrow = g_h + (size_t)m * H_;

    float acc[16];
#pragma unroll
    for (int k = 0; k < 16; k++) acc[k] = b2[k];

    for (int hh = 0; hh < H_; hh += 4) {
        float4 hv = *(const float4*)(hrow + hh);
        float hs[4] = {hv.x, hv.y, hv.z, hv.w};
#pragma unroll
        for (int u = 0; u < 4; u++) {
            const float4* wr = (const float4*)(W2 + (size_t)(hh + u) * 16);
#pragma unroll
            for (int k4 = 0; k4 < 4; k4++) {
                float4 w = __ldg(&wr[k4]);
                acc[k4 * 4 + 0] = fmaf(hs[u], w.x, acc[k4 * 4 + 0]);
                acc[k4 * 4 + 1] = fmaf(hs[u], w.y, acc[k4 * 4 + 1]);
                acc[k4 * 4 + 2] = fmaf(hs[u], w.z, acc[k4 * 4 + 2]);
                acc[k4 * 4 + 3] = fmaf(hs[u], w.w, acc[k4 * 4 + 3]);
            }
        }
    }

    float4* out = (float4*)(g_em + (size_t)m * 16);
#pragma unroll
    for (int k4 = 0; k4 < 4; k4++) {
        float4 v;
        v.x = acc[k4 * 4 + 0];
        v.y = acc[k4 * 4 + 1];
        v.z = acc[k4 * 4 + 2];
        v.w = acc[k4 * 4 + 3];
        out[k4] = v;
    }
}

// ---------------------------------------------------------------------------
// CRF forward scan + gold path. One warp per batch element.
// Lane j (j = lane & 15) owns state j; linear-domain recurrence:
//   alpha'_j = m + log( sum_i exp(alpha_i - m) * exp(T[j,i]) ) + em[t,b,j]
// ---------------------------------------------------------------------------
__global__ __launch_bounds__(32) void crf_kernel(
    const float* __restrict__ trans,  // (K x K)
    const int*   __restrict__ lens,   // (B)
    const int*   __restrict__ tags)   // (T x B)
{
    const int b    = blockIdx.x;
    const int lane = threadIdx.x;
    const int j    = lane & 15;
    const int len  = lens[b];
    const unsigned FULL = 0xffffffffu;

    // ---- gold path: parallel sum over t (same addend set as ref cumsum) ----
    float gsum = 0.f;
    for (int t = lane; t < len; t += 32) {
        int tag = tags[t * B_ + b];
        gsum += g_em[((size_t)t * B_ + b) * K_ + tag];
        if (t >= 1) {
            int tprev = tags[(t - 1) * B_ + b];
            gsum += trans[tag * K_ + tprev];
        }
    }
#pragma unroll
    for (int o = 16; o > 0; o >>= 1)
        gsum += __shfl_xor_sync(FULL, gsum, o);

    // ---- forward scan ----
    float eT[16];
#pragma unroll
    for (int i = 0; i < 16; i++) eT[i] = __expf(trans[j * 16 + i]);

    float alpha = g_em[(size_t)b * K_ + j];   // t = 0
    float e_next = g_em[((size_t)1 * B_ + b) * K_ + j];

    for (int t = 1; t < len; t++) {
        float e_cur = e_next;
        if (t + 1 < len)
            e_next = g_em[((size_t)(t + 1) * B_ + b) * K_ + j];

        // m = max over the 16 states
        float m = alpha;
#pragma unroll
        for (int o = 8; o > 0; o >>= 1)
            m = fmaxf(m, __shfl_xor_sync(FULL, m, o, 16));

        float p = __expf(alpha - m);
        float s = 0.f;
#pragma unroll
        for (int i = 0; i < 16; i++) {
            float pi = __shfl_sync(FULL, p, i, 16);
            s = fmaf(pi, eT[i], s);
        }
        alpha = m + __logf(s) + e_cur;
    }

    // fwd = logsumexp(alpha at t = len-1)
    float m2 = alpha;
#pragma unroll
    for (int o = 8; o > 0; o >>= 1)
        m2 = fmaxf(m2, __shfl_xor_sync(FULL, m2, o, 16));
    float s2 = __expf(alpha - m2);
#pragma unroll
    for (int o = 8; o > 0; o >>= 1)
        s2 += __shfl_xor_sync(FULL, s2, o, 16);
    float fwd = m2 + __logf(s2);

    if (lane == 0) g_diff[b] = fwd - gsum;
}

// ---------------------------------------------------------------------------
// Deterministic final reduce
// ---------------------------------------------------------------------------
__global__ void reduce_kernel(float* __restrict__ out)
{
    if (threadIdx.x == 0) {
        float s = 0.f;
        for (int b = 0; b < B_; b++) s += g_diff[b];
        out[0] = s;
    }
}

// ---------------------------------------------------------------------------
extern "C" void kernel_launch(void* const* d_in, const int* in_sizes, int n_in,
                              void* d_out, int out_size)
{
    const float* hidden = (const float*)d_in[0];
    const float* W1     = (const float*)d_in[1];
    const float* b1     = (const float*)d_in[2];
    const float* W2     = (const float*)d_in[3];
    const float* b2     = (const float*)d_in[4];
    const float* trans  = (const float*)d_in[5];
    const int*   lens   = (const int*)d_in[6];
    const int*   tags   = (const int*)d_in[7];
    float* out = (float*)d_out;

    dim3 g1(H_ / BN, M_ / BM);            // (4, 256)
    gemm1_kernel<<<g1, 256>>>(hidden, W1, b1);
    gemm2_kernel<<<M_ / 256, 256>>>(W2, b2);
    crf_kernel<<<B_, 32>>>(trans, lens, tags);
    reduce_kernel<<<1, 32>>>(out);
}

// round 6
// speedup vs baseline: 2.4371x; 2.4371x over previous
#include <cuda_runtime.h>
#include <cuda_bf16.h>
#include <cstdint>

// Problem constants
constexpr int T_ = 512;
constexpr int B_ = 64;
constexpr int H_ = 512;
constexpr int K_ = 16;
constexpr int M_ = T_ * B_;   // 32768 rows

// Scratch (device globals — no allocation allowed)
__device__ __nv_bfloat16 g_h[(size_t)M_ * H_];   // 32 MB: relu(hidden@W1+b1), bf16
__device__ float g_em[(size_t)M_ * K_];          // 2 MB : h@W2+b2
__device__ float g_diff[B_];                     // per-batch fwd - gold
__device__ unsigned g_count = 0;                 // last-block counter (self-resetting)

// ---------------------------------------------------------------------------
// PTX helpers
// ---------------------------------------------------------------------------
__device__ __forceinline__ void ldsm_x4(uint32_t& r0, uint32_t& r1, uint32_t& r2,
                                        uint32_t& r3, uint32_t addr) {
    asm volatile("ldmatrix.sync.aligned.m8n8.x4.shared.b16 {%0,%1,%2,%3}, [%4];"
                 : "=r"(r0), "=r"(r1), "=r"(r2), "=r"(r3) : "r"(addr));
}
__device__ __forceinline__ void ldsm_x2_trans(uint32_t& r0, uint32_t& r1, uint32_t addr) {
    asm volatile("ldmatrix.sync.aligned.m8n8.x2.trans.shared.b16 {%0,%1}, [%2];"
                 : "=r"(r0), "=r"(r1) : "r"(addr));
}
__device__ __forceinline__ void mma16816(float* c, const uint32_t* a, const uint32_t* b) {
    asm volatile(
        "mma.sync.aligned.m16n8k16.row.col.f32.bf16.bf16.f32 "
        "{%0,%1,%2,%3}, {%4,%5,%6,%7}, {%8,%9}, {%0,%1,%2,%3};"
        : "+f"(c[0]), "+f"(c[1]), "+f"(c[2]), "+f"(c[3])
        : "r"(a[0]), "r"(a[1]), "r"(a[2]), "r"(a[3]), "r"(b[0]), "r"(b[1]));
}

// ---------------------------------------------------------------------------
// GEMM1: g_h = relu(hidden @ W1 + b1)  — bf16 tensor cores, fp32 accum
// M=32768, N=512, K=512.  BM=128, BN=128, BK=32, 256 threads (8 warps 2x4),
// warp tile 64x32 (4 m16-tiles x 4 n8-tiles).
// ---------------------------------------------------------------------------
#define BM 128
#define BN 128
#define BK 32

__global__ __launch_bounds__(256) void gemm1_kernel(
    const float* __restrict__ A,      // hidden  (M x H) fp32
    const float* __restrict__ W,      // W1      (H x H) fp32
    const float* __restrict__ bias)   // b1      (H)
{
    __shared__ __align__(16) __nv_bfloat16 As[BM][40];   // stride 80B (16B-mult)
    __shared__ __align__(16) __nv_bfloat16 Bs[BK][136];  // stride 272B (16B-mult)

    const int bm   = blockIdx.y * BM;
    const int bn   = blockIdx.x * BN;
    const int tid  = threadIdx.x;
    const int lane = tid & 31;
    const int warp = tid >> 5;
    const int wm   = warp >> 2;       // 0..1 -> 64 rows
    const int wn   = warp & 3;        // 0..3 -> 32 cols

    float acc[4][4][4];
#pragma unroll
    for (int mi = 0; mi < 4; mi++)
#pragma unroll
        for (int ni = 0; ni < 4; ni++)
#pragma unroll
            for (int r = 0; r < 4; r++) acc[mi][ni][r] = 0.f;

    // load index mapping
    const int arow = tid >> 1;              // 0..127
    const int acol = (tid & 1) * 16;        // 0 / 16
    const int brow = tid >> 3;              // 0..31
    const int bcol = (tid & 7) * 16;        // 0..112

    for (int k0 = 0; k0 < H_; k0 += BK) {
        // ---- A tile 128x32 fp32 -> bf16 smem ----
        {
            const float4* src = (const float4*)&A[(size_t)(bm + arow) * H_ + k0 + acol];
            float4 v0 = src[0], v1 = src[1], v2 = src[2], v3 = src[3];
            __nv_bfloat162* dst = (__nv_bfloat162*)&As[arow][acol];
            dst[0] = __floats2bfloat162_rn(v0.x, v0.y);
            dst[1] = __floats2bfloat162_rn(v0.z, v0.w);
            dst[2] = __floats2bfloat162_rn(v1.x, v1.y);
            dst[3] = __floats2bfloat162_rn(v1.z, v1.w);
            dst[4] = __floats2bfloat162_rn(v2.x, v2.y);
            dst[5] = __floats2bfloat162_rn(v2.z, v2.w);
            dst[6] = __floats2bfloat162_rn(v3.x, v3.y);
            dst[7] = __floats2bfloat162_rn(v3.z, v3.w);
        }
        // ---- B tile 32x128 fp32 -> bf16 smem ----
        {
            const float4* src = (const float4*)&W[(size_t)(k0 + brow) * H_ + bn + bcol];
            float4 v0 = src[0], v1 = src[1], v2 = src[2], v3 = src[3];
            __nv_bfloat162* dst = (__nv_bfloat162*)&Bs[brow][bcol];
            dst[0] = __floats2bfloat162_rn(v0.x, v0.y);
            dst[1] = __floats2bfloat162_rn(v0.z, v0.w);
            dst[2] = __floats2bfloat162_rn(v1.x, v1.y);
            dst[3] = __floats2bfloat162_rn(v1.z, v1.w);
            dst[4] = __floats2bfloat162_rn(v2.x, v2.y);
            dst[5] = __floats2bfloat162_rn(v2.z, v2.w);
            dst[6] = __floats2bfloat162_rn(v3.x, v3.y);
            dst[7] = __floats2bfloat162_rn(v3.z, v3.w);
        }
        __syncthreads();

#pragma unroll
        for (int ks = 0; ks < BK; ks += 16) {
            uint32_t af[4][4];
#pragma unroll
            for (int mi = 0; mi < 4; mi++) {
                int r = wm * 64 + mi * 16 + (lane & 15);
                int c = ks + ((lane >> 4) << 3);
                uint32_t addr = (uint32_t)__cvta_generic_to_shared(&As[r][c]);
                ldsm_x4(af[mi][0], af[mi][1], af[mi][2], af[mi][3], addr);
            }
            uint32_t bf[4][2];
#pragma unroll
            for (int ni = 0; ni < 4; ni++) {
                int r = ks + (lane & 15);
                int c = wn * 32 + ni * 8;
                uint32_t addr = (uint32_t)__cvta_generic_to_shared(&Bs[r][c]);
                ldsm_x2_trans(bf[ni][0], bf[ni][1], addr);
            }
#pragma unroll
            for (int mi = 0; mi < 4; mi++)
#pragma unroll
                for (int ni = 0; ni < 4; ni++)
                    mma16816(acc[mi][ni], af[mi], bf[ni]);
        }
        __syncthreads();
    }

    // ---- epilogue: bias + relu -> bf16 g_h ----
    const int groupID = lane >> 2;
    const int tig     = lane & 3;
#pragma unroll
    for (int ni = 0; ni < 4; ni++) {
        int col = bn + wn * 32 + ni * 8 + tig * 2;
        float b0 = __ldg(&bias[col]);
        float b1v = __ldg(&bias[col + 1]);
#pragma unroll
        for (int mi = 0; mi < 4; mi++) {
            int row0 = bm + wm * 64 + mi * 16 + groupID;
            int row1 = row0 + 8;
            float c0 = fmaxf(acc[mi][ni][0] + b0, 0.f);
            float c1 = fmaxf(acc[mi][ni][1] + b1v, 0.f);
            float c2 = fmaxf(acc[mi][ni][2] + b0, 0.f);
            float c3 = fmaxf(acc[mi][ni][3] + b1v, 0.f);
            *(__nv_bfloat162*)&g_h[(size_t)row0 * H_ + col] = __floats2bfloat162_rn(c0, c1);
            *(__nv_bfloat162*)&g_h[(size_t)row1 * H_ + col] = __floats2bfloat162_rn(c2, c3);
        }
    }
}

// ---------------------------------------------------------------------------
// GEMM2: em = h @ W2 + b2   (M x 512 bf16) @ (512 x 16 fp32)
// W2 staged in smem (broadcast reads). One thread per output row.
// ---------------------------------------------------------------------------
__global__ __launch_bounds__(256) void gemm2_kernel(
    const float* __restrict__ W2,     // (H x K)
    const float* __restrict__ b2)     // (K)
{
    __shared__ float W2s[H_ * K_];    // 32 KB
    const int tid = threadIdx.x;
    for (int i = tid; i < H_ * K_; i += 256) W2s[i] = W2[i];
    __syncthreads();

    const int m = blockIdx.x * 256 + tid;
    const __nv_bfloat16* hrow = g_h + (size_t)m * H_;

    float acc[16];
#pragma unroll
    for (int k = 0; k < 16; k++) acc[k] = b2[k];

    for (int hh = 0; hh < H_; hh += 8) {
        float4 raw = *(const float4*)(hrow + hh);         // 8 bf16
        const __nv_bfloat162* p = (const __nv_bfloat162*)&raw;
#pragma unroll
        for (int u = 0; u < 4; u++) {
            float2 hv = __bfloat1622float2(p[u]);
            const float* w0 = &W2s[(hh + 2 * u) * 16];
            const float* w1 = w0 + 16;
#pragma unroll
            for (int k = 0; k < 16; k++) {
                acc[k] = fmaf(hv.x, w0[k], acc[k]);
                acc[k] = fmaf(hv.y, w1[k], acc[k]);
            }
        }
    }

    float4* out = (float4*)(g_em + (size_t)m * 16);
#pragma unroll
    for (int k4 = 0; k4 < 4; k4++) {
        float4 v;
        v.x = acc[k4 * 4 + 0];
        v.y = acc[k4 * 4 + 1];
        v.z = acc[k4 * 4 + 2];
        v.w = acc[k4 * 4 + 3];
        out[k4] = v;
    }
}

// ---------------------------------------------------------------------------
// CRF forward scan + gold path + final reduce. One warp per batch element.
// Linear-domain recurrence with lagged lane-0 rescale (off critical path):
//   a'_j = (sum_i eT[j][i] * a_i) * (exp(em_tj) / c),  c = a_0 (prev step)
//   L   += log(c)   (off-chain);  alpha_j = L + log(a_j)
// ---------------------------------------------------------------------------
__global__ __launch_bounds__(32) void crf_kernel(
    const float* __restrict__ trans,  // (K x K)
    const int*   __restrict__ lens,   // (B)
    const int*   __restrict__ tags,   // (T x B)
    float*       __restrict__ out)
{
    const int b    = blockIdx.x;
    const int lane = threadIdx.x;
    const int j    = lane & 15;
    const int len  = lens[b];
    const unsigned FULL = 0xffffffffu;

    // ---- gold path: parallel sum over t (same addend set as ref cumsum) ----
    float gsum = 0.f;
    for (int t = lane; t < len; t += 32) {
        int tag = tags[t * B_ + b];
        gsum += g_em[((size_t)t * B_ + b) * K_ + tag];
        if (t >= 1) {
            int tprev = tags[(t - 1) * B_ + b];
            gsum += trans[tag * K_ + tprev];
        }
    }
#pragma unroll
    for (int o = 16; o > 0; o >>= 1)
        gsum += __shfl_xor_sync(FULL, gsum, o);

    // ---- forward scan (linear domain) ----
    float eT[16];
#pragma unroll
    for (int i = 0; i < 16; i++) eT[i] = __expf(trans[j * 16 + i]);

    float em0  = g_em[(size_t)b * K_ + j];                  // t = 0
    float em00 = __shfl_sync(FULL, em0, 0, 16);
    float a = __expf(em0 - em00);                            // lane0 == 1
    float L = em00;

    float enext = __expf(g_em[((size_t)1 * B_ + b) * K_ + j]);

    for (int t = 1; t < len; t++) {
        float eem = enext;
        if (t + 1 < len)
            enext = __expf(g_em[((size_t)(t + 1) * B_ + b) * K_ + j]);

        float c = __shfl_sync(FULL, a, 0, 16);   // prev-step lane0 (lagged norm)
        float scale = __fdividef(eem, c);        // off sum-chain
        L += __logf(c);                          // off-chain

        float s0 = 0.f, s1 = 0.f, s2 = 0.f, s3 = 0.f;
#pragma unroll
        for (int i = 0; i < 4; i++) {
            s0 = fmaf(__shfl_sync(FULL, a, i,      16), eT[i],      s0);
            s1 = fmaf(__shfl_sync(FULL, a, 4 + i,  16), eT[4 + i],  s1);
            s2 = fmaf(__shfl_sync(FULL, a, 8 + i,  16), eT[8 + i],  s2);
            s3 = fmaf(__shfl_sync(FULL, a, 12 + i, 16), eT[12 + i], s3);
        }
        a = ((s0 + s1) + (s2 + s3)) * scale;
    }

    // fwd = L + log(sum_j a_j)
    float ssum = a;
#pragma unroll
    for (int o = 8; o > 0; o >>= 1)
        ssum += __shfl_xor_sync(FULL, ssum, o, 16);
    float fwd = L + __logf(ssum);

    if (lane == 0) {
        g_diff[b] = fwd - gsum;
        __threadfence();
        unsigned prev = atomicAdd(&g_count, 1);
        if (prev == B_ - 1) {                       // last block: fixed-order sum
            __threadfence();
            const volatile float* gd = g_diff;
            float s = 0.f;
            for (int i = 0; i < B_; i++) s += gd[i];
            *out = s;
            g_count = 0;                            // reset for graph replay
        }
    }
}

// ---------------------------------------------------------------------------
extern "C" void kernel_launch(void* const* d_in, const int* in_sizes, int n_in,
                              void* d_out, int out_size)
{
    const float* hidden = (const float*)d_in[0];
    const float* W1     = (const float*)d_in[1];
    const float* b1     = (const float*)d_in[2];
    const float* W2     = (const float*)d_in[3];
    const float* b2     = (const float*)d_in[4];
    const float* trans  = (const float*)d_in[5];
    const int*   lens   = (const int*)d_in[6];
    const int*   tags   = (const int*)d_in[7];
    float* out = (float*)d_out;

    dim3 g1(H_ / BN, M_ / BM);            // (4, 256)
    gemm1_kernel<<<g1, 256>>>(hidden, W1, b1);
    gemm2_kernel<<<M_ / 256, 256>>>(W2, b2);
    crf_kernel<<<B_, 32>>>(trans, lens, tags, out);
}

// round 12
// speedup vs baseline: 2.7761x; 1.1391x over previous
#include <cuda_runtime.h>
#include <cuda_bf16.h>
#include <cstdint>

// Problem constants
constexpr int T_ = 512;
constexpr int B_ = 64;
constexpr int H_ = 512;
constexpr int K_ = 16;
constexpr int M_ = T_ * B_;   // 32768 rows

// Scratch (device globals — no allocation allowed)
__device__ __align__(16) __nv_bfloat16 g_h[(size_t)M_ * H_];   // 32 MB
__device__ __align__(16) __nv_bfloat16 g_w1t[H_ * H_];         // 512 KB: W1^T bf16 [n][k]
__device__ float g_em[(size_t)M_ * K_];                        // 2 MB
__device__ float g_stepT[B_ * T_];                             // 128 KB: gold steps [b][t]
__device__ float g_diff[B_];
__device__ unsigned g_count = 0;

// ---------------------------------------------------------------------------
// PTX helpers
// ---------------------------------------------------------------------------
__device__ __forceinline__ uint32_t smem_u32(const void* p) {
    uint32_t a;
    asm("{ .reg .u64 t; cvta.to.shared.u64 t, %1; cvt.u32.u64 %0, t; }" : "=r"(a) : "l"(p));
    return a;
}
__device__ __forceinline__ void ldsm_x4(uint32_t& r0, uint32_t& r1, uint32_t& r2,
                                        uint32_t& r3, uint32_t addr) {
    asm volatile("ldmatrix.sync.aligned.m8n8.x4.shared.b16 {%0,%1,%2,%3}, [%4];"
                 : "=r"(r0), "=r"(r1), "=r"(r2), "=r"(r3) : "r"(addr));
}
__device__ __forceinline__ void mma16816(float* c, const uint32_t* a, const uint32_t* b) {
    asm volatile(
        "mma.sync.aligned.m16n8k16.row.col.f32.bf16.bf16.f32 "
        "{%0,%1,%2,%3}, {%4,%5,%6,%7}, {%8,%9}, {%0,%1,%2,%3};"
        : "+f"(c[0]), "+f"(c[1]), "+f"(c[2]), "+f"(c[3])
        : "r"(a[0]), "r"(a[1]), "r"(a[2]), "r"(a[3]), "r"(b[0]), "r"(b[1]));
}
__device__ __forceinline__ void cp16(uint32_t dst, const void* src) {
    asm volatile("cp.async.cg.shared.global [%0], [%1], 16;" :: "r"(dst), "l"(src));
}
__device__ __forceinline__ void cp_commit() {
    asm volatile("cp.async.commit_group;");
}
__device__ __forceinline__ void cp_wait2() {
    asm volatile("cp.async.wait_group 2;");
}

// ---------------------------------------------------------------------------
// prep: g_w1t[n][k] = bf16(W1[k][n])
// ---------------------------------------------------------------------------
__global__ void prep_w1t(const float* __restrict__ W1)
{
    __shared__ float t[32][33];
    const int bx = blockIdx.x * 32, by = blockIdx.y * 32;
    const int tx = threadIdx.x, ty = threadIdx.y;   // 32 x 8
#pragma unroll
    for (int r = 0; r < 32; r += 8)
        t[ty + r][tx] = W1[(size_t)(by + ty + r) * H_ + bx + tx];
    __syncthreads();
#pragma unroll
    for (int r = 0; r < 32; r += 8)
        g_w1t[(size_t)(bx + ty + r) * H_ + by + tx] = __float2bfloat16(t[tx][ty + r]);
}

// ---------------------------------------------------------------------------
// GEMM1: g_h = relu(hidden @ W1 + b1) — mma.sync bf16, pipelined.
// BM=128, BN=256, BK=32. 8 warps (2m x 4n), warp tile 64x64 (4m x 8n tiles).
// B: 3-stage cp.async from g_w1t [n][k].  A: reg-staged LDG fp32 -> cvt -> STS.
// smem rows padded to 40 bf16 (80B, 16B-aligned, conflict-light).
// ---------------------------------------------------------------------------
#define ABUF_STRIDE 10240u            // 128*40*2 per stage (2 stages)
#define BBUF_STRIDE 20480u            // 256*40*2 per stage (3 stages)
#define SMEM_TOTAL  (2*10240 + 3*20480)   // 81920
#define NSTAGE 16                     // 512/32

__global__ __launch_bounds__(256, 1) void gemm1_kernel(
    const float* __restrict__ A,      // hidden (M x H) fp32
    const float* __restrict__ bias)   // b1 (H)
{
    extern __shared__ __align__(16) char smem[];
    char* Abuf = smem;                       // [2][128][40] bf16
    char* Bbuf = smem + 2 * ABUF_STRIDE;     // [3][256][40] bf16
    const uint32_t ab = smem_u32(Abuf);
    const uint32_t bb = smem_u32(Bbuf);

    const int tid  = threadIdx.x;
    const int lane = tid & 31;
    const int warp = tid >> 5;
    const int wm   = warp >> 2;       // 0..1
    const int wn   = warp & 3;        // 0..3
    const int bm   = blockIdx.y * 128;
    const int bn   = blockIdx.x * 256;

    float acc[4][8][4];
#pragma unroll
    for (int mi = 0; mi < 4; mi++)
#pragma unroll
        for (int nj = 0; nj < 8; nj++)
#pragma unroll
            for (int r = 0; r < 4; r++) acc[mi][nj][r] = 0.f;

    // --- B stage issue: 256 rows x 32 k bf16 = 1024 x 16B, 4/thread ---
    const int brow = tid >> 2;                // reused row base per i-iter
    const int bch  = tid & 3;
    auto issueB = [&](int st, int buf) {
        const uint32_t dstb = bb + (uint32_t)buf * BBUF_STRIDE;
#pragma unroll
        for (int i = 0; i < 4; i++) {
            int row = brow + i * 64;
            uint32_t dst = dstb + (uint32_t)row * 80u + (uint32_t)bch * 16u;
            const void* src = (const void*)(g_w1t + (size_t)(bn + row) * H_ + st * 32 + bch * 8);
            cp16(dst, src);
        }
        cp_commit();
    };

    // --- A stage: 128 rows x 32 k fp32; thread: row=tid>>1, half=tid&1 ---
    const int arow  = tid >> 1;
    const int ahalf = tid & 1;
    float4 ar[4];
    auto ldgA = [&](int st) {
        const float4* p = (const float4*)(A + (size_t)(bm + arow) * H_ + st * 32 + ahalf * 16);
        ar[0] = p[0]; ar[1] = p[1]; ar[2] = p[2]; ar[3] = p[3];
    };
    auto stsA = [&](int buf) {
        __nv_bfloat162 q[8];
        q[0] = __floats2bfloat162_rn(ar[0].x, ar[0].y);
        q[1] = __floats2bfloat162_rn(ar[0].z, ar[0].w);
        q[2] = __floats2bfloat162_rn(ar[1].x, ar[1].y);
        q[3] = __floats2bfloat162_rn(ar[1].z, ar[1].w);
        q[4] = __floats2bfloat162_rn(ar[2].x, ar[2].y);
        q[5] = __floats2bfloat162_rn(ar[2].z, ar[2].w);
        q[6] = __floats2bfloat162_rn(ar[3].x, ar[3].y);
        q[7] = __floats2bfloat162_rn(ar[3].z, ar[3].w);
        char* dst = Abuf + buf * ABUF_STRIDE + arow * 80 + ahalf * 32;
        ((uint4*)dst)[0] = ((const uint4*)q)[0];
        ((uint4*)dst)[1] = ((const uint4*)q)[1];
    };

    // prologue
    issueB(0, 0); issueB(1, 1); issueB(2, 2);
    ldgA(0);

    // frag address bases (per-thread constants)
    const uint32_t a_row_off = (uint32_t)(wm * 64 + (lane & 15)) * 80u + (uint32_t)((lane >> 4) * 16);
    const uint32_t b_row_off = (uint32_t)(wn * 64 + (lane & 7) + ((lane >> 4) << 3)) * 80u
                             + (uint32_t)(((lane >> 3) & 1) * 16);

#pragma unroll 1
    for (int s = 0; s < NSTAGE; s++) {
        const int abuf = s & 1;
        stsA(abuf);
        cp_wait2();
        __syncthreads();

        if (s + 1 < NSTAGE) ldgA(s + 1);

        // ldmatrix all fragments for this stage (2 ksteps)
        uint32_t afr[2][4][4], bfr[2][4][4];
#pragma unroll
        for (int ks = 0; ks < 2; ks++) {
#pragma unroll
            for (int mi = 0; mi < 4; mi++) {
                uint32_t addr = ab + abuf * ABUF_STRIDE + a_row_off
                              + (uint32_t)(mi * 16) * 80u + (uint32_t)(ks * 32);
                ldsm_x4(afr[ks][mi][0], afr[ks][mi][1], afr[ks][mi][2], afr[ks][mi][3], addr);
            }
#pragma unroll
            for (int np = 0; np < 4; np++) {
                uint32_t addr = bb + (uint32_t)(s % 3) * BBUF_STRIDE + b_row_off
                              + (uint32_t)(np * 16) * 80u + (uint32_t)(ks * 32);
                ldsm_x4(bfr[ks][np][0], bfr[ks][np][1], bfr[ks][np][2], bfr[ks][np][3], addr);
            }
        }
        __syncthreads();   // all warps done reading Bbuf[s%3] before refill

        if (s + 3 < NSTAGE) issueB(s + 3, s % 3);
        else                cp_commit();      // keep wait_group bookkeeping

        // mma
#pragma unroll
        for (int ks = 0; ks < 2; ks++)
#pragma unroll
            for (int mi = 0; mi < 4; mi++)
#pragma unroll
                for (int nj = 0; nj < 8; nj++) {
                    const uint32_t* bp = (nj & 1) ? &bfr[ks][nj >> 1][2] : &bfr[ks][nj >> 1][0];
                    mma16816(acc[mi][nj], afr[ks][mi], bp);
                }
    }

    // ---- epilogue: bias + relu -> bf16 g_h ----
    const int g   = lane >> 2;
    const int tig = lane & 3;
#pragma unroll
    for (int nj = 0; nj < 8; nj++) {
        int col = bn + wn * 64 + nj * 8 + tig * 2;
        float b0 = __ldg(&bias[col]);
        float b1 = __ldg(&bias[col + 1]);
#pragma unroll
        for (int mi = 0; mi < 4; mi++) {
            int row0 = bm + wm * 64 + mi * 16 + g;
            int row1 = row0 + 8;
            float c0 = fmaxf(acc[mi][nj][0] + b0, 0.f);
            float c1 = fmaxf(acc[mi][nj][1] + b1, 0.f);
            float c2 = fmaxf(acc[mi][nj][2] + b0, 0.f);
            float c3 = fmaxf(acc[mi][nj][3] + b1, 0.f);
            *(__nv_bfloat162*)&g_h[(size_t)row0 * H_ + col] = __floats2bfloat162_rn(c0, c1);
            *(__nv_bfloat162*)&g_h[(size_t)row1 * H_ + col] = __floats2bfloat162_rn(c2, c3);
        }
    }
}

// ---------------------------------------------------------------------------
// GEMM2: em = h @ W2 + b2, plus gold-path steps g_stepT[b][t].
// ---------------------------------------------------------------------------
__global__ __launch_bounds__(256) void gemm2_kernel(
    const float* __restrict__ W2, const float* __restrict__ b2,
    const float* __restrict__ trans, const int* __restrict__ tags)
{
    __shared__ float W2s[H_ * K_];    // 32 KB
    __shared__ float Ts[K_ * K_];     // 1 KB
    const int tid = threadIdx.x;
    for (int i = tid; i < H_ * K_; i += 256) W2s[i] = W2[i];
    if (tid < 256) Ts[tid] = trans[tid];
    __syncthreads();

    const int m = blockIdx.x * 256 + tid;
    const __nv_bfloat16* hrow = g_h + (size_t)m * H_;

    float acc[16];
#pragma unroll
    for (int k = 0; k < 16; k++) acc[k] = b2[k];

    for (int hh = 0; hh < H_; hh += 8) {
        float4 raw = *(const float4*)(hrow + hh);
        const __nv_bfloat162* p = (const __nv_bfloat162*)&raw;
#pragma unroll
        for (int u = 0; u < 4; u++) {
            float2 hv = __bfloat1622float2(p[u]);
            const float* w0 = &W2s[(hh + 2 * u) * 16];
            const float* w1 = w0 + 16;
#pragma unroll
            for (int k = 0; k < 16; k++) {
                acc[k] = fmaf(hv.x, w0[k], acc[k]);
                acc[k] = fmaf(hv.y, w1[k], acc[k]);
            }
        }
    }

    float4* out = (float4*)(g_em + (size_t)m * 16);
#pragma unroll
    for (int k4 = 0; k4 < 4; k4++) {
        float4 v;
        v.x = acc[k4 * 4 + 0]; v.y = acc[k4 * 4 + 1];
        v.z = acc[k4 * 4 + 2]; v.w = acc[k4 * 4 + 3];
        out[k4] = v;
    }

    // gold step, transposed for coalesced CRF reads
    const int t = m >> 6;           // m = t*64 + b
    const int b = m & 63;
    int tag = tags[m];
    float step = acc[tag];
    if (t > 0) {
        int tp = tags[m - B_];
        step += Ts[tag * 16 + tp];
    }
    g_stepT[b * T_ + t] = step;
}

// ---------------------------------------------------------------------------
// CRF forward scan + gold sum + fused final reduce. One warp per batch.
// ---------------------------------------------------------------------------
__global__ __launch_bounds__(32) void crf_kernel(
    const float* __restrict__ trans,
    const int*   __restrict__ lens,
    float*       __restrict__ out)
{
    const int b    = blockIdx.x;
    const int lane = threadIdx.x;
    const int j    = lane & 15;
    const int len  = lens[b];
    const unsigned FULL = 0xffffffffu;

    // gold: coalesced streaming sum of precomputed steps
    float gsum = 0.f;
    for (int t = lane; t < len; t += 32)
        gsum += g_stepT[b * T_ + t];
#pragma unroll
    for (int o = 16; o > 0; o >>= 1)
        gsum += __shfl_xor_sync(FULL, gsum, o);

    // forward scan (linear domain, lagged lane-0 normalizer)
    float eT[16];
#pragma unroll
    for (int i = 0; i < 16; i++) eT[i] = __expf(trans[j * 16 + i]);

    float em0  = g_em[(size_t)b * K_ + j];
    float em00 = __shfl_sync(FULL, em0, 0, 16);
    float a = __expf(em0 - em00);
    float L = em00;

    float enext = __expf(g_em[((size_t)1 * B_ + b) * K_ + j]);

    for (int t = 1; t < len; t++) {
        float eem = enext;
        if (t + 1 < len)
            enext = __expf(g_em[((size_t)(t + 1) * B_ + b) * K_ + j]);

        float c = __shfl_sync(FULL, a, 0, 16);
        float scale = __fdividef(eem, c);
        L += __logf(c);

        float s0 = 0.f, s1 = 0.f, s2 = 0.f, s3 = 0.f;
#pragma unroll
        for (int i = 0; i < 4; i++) {
            s0 = fmaf(__shfl_sync(FULL, a, i,      16), eT[i],      s0);
            s1 = fmaf(__shfl_sync(FULL, a, 4 + i,  16), eT[4 + i],  s1);
            s2 = fmaf(__shfl_sync(FULL, a, 8 + i,  16), eT[8 + i],  s2);
            s3 = fmaf(__shfl_sync(FULL, a, 12 + i, 16), eT[12 + i], s3);
        }
        a = ((s0 + s1) + (s2 + s3)) * scale;
    }

    float ssum = a;
#pragma unroll
    for (int o = 8; o > 0; o >>= 1)
        ssum += __shfl_xor_sync(FULL, ssum, o, 16);
    float fwd = L + __logf(ssum);

    if (lane == 0) {
        g_diff[b] = fwd - gsum;
        __threadfence();
        unsigned prev = atomicAdd(&g_count, 1);
        if (prev == B_ - 1) {
            __threadfence();
            const volatile float* gd = g_diff;
            float s = 0.f;
            for (int i = 0; i < B_; i++) s += gd[i];
            *out = s;
            g_count = 0;    // reset for graph replay
        }
    }
}

// ---------------------------------------------------------------------------
extern "C" void kernel_launch(void* const* d_in, const int* in_sizes, int n_in,
                              void* d_out, int out_size)
{
    const float* hidden = (const float*)d_in[0];
    const float* W1     = (const float*)d_in[1];
    const float* b1     = (const float*)d_in[2];
    const float* W2     = (const float*)d_in[3];
    const float* b2     = (const float*)d_in[4];
    const float* trans  = (const float*)d_in[5];
    const int*   lens   = (const int*)d_in[6];
    const int*   tags   = (const int*)d_in[7];
    float* out = (float*)d_out;

    cudaFuncSetAttribute(gemm1_kernel, cudaFuncAttributeMaxDynamicSharedMemorySize, SMEM_TOTAL);

    prep_w1t<<<dim3(16, 16), dim3(32, 8)>>>(W1);
    gemm1_kernel<<<dim3(H_ / 256, M_ / 128), 256, SMEM_TOTAL>>>(hidden, b1);
    gemm2_kernel<<<M_ / 256, 256>>>(W2, b2, trans, tags);
    crf_kernel<<<B_, 32>>>(trans, lens, out);
}